// round 14
// baseline (speedup 1.0000x reference)
#include <cuda_runtime.h>
#include <cuda_fp16.h>
#include <stdint.h>

#define T_TOK 32768
#define DIM   1024
#define FF    2048
#define NE    8

#define TM 64
#define TN 128

// ---------------- device scratch ----------------
__device__ int    g_counts[NE];
__device__ int    g_tok [NE * T_TOK];
__device__ float  g_gate[NE * T_TOK];
__device__ __half g_xh [(size_t)T_TOK * DIM];
__device__ __half g_w1h[(size_t)NE * FF * DIM];
__device__ __half g_w2h[(size_t)NE * DIM * FF];
__device__ __half g_h  [(size_t)T_TOK * 2 * FF];

// ---------------- helpers ----------------
__device__ __forceinline__ void cp16(void* smem, const void* gmem) {
    uint32_t s = (uint32_t)__cvta_generic_to_shared(smem);
    asm volatile("cp.async.cg.shared.global [%0], [%1], 16;\n" :: "r"(s), "l"(gmem));
}
#define CP_COMMIT() asm volatile("cp.async.commit_group;\n" ::: "memory")
#define CP_WAIT(n)  asm volatile("cp.async.wait_group %0;\n" :: "n"(n) : "memory")

__device__ __forceinline__ void mma16816(float* c, const uint32_t* a, uint32_t b0, uint32_t b1) {
    asm volatile(
        "mma.sync.aligned.m16n8k16.row.col.f32.f16.f16.f32 "
        "{%0,%1,%2,%3}, {%4,%5,%6,%7}, {%8,%9}, {%0,%1,%2,%3};\n"
        : "+f"(c[0]), "+f"(c[1]), "+f"(c[2]), "+f"(c[3])
        : "r"(a[0]), "r"(a[1]), "r"(a[2]), "r"(a[3]), "r"(b0), "r"(b1));
}

__device__ __forceinline__ float silu_f(float v) {
    return v * __frcp_rn(1.0f + __expf(-v));
}

// ---------------- prep kernels ----------------
__global__ void zero_out_kernel(float4* out, int n4) {
    int i = blockIdx.x * blockDim.x + threadIdx.x;
    int stride = gridDim.x * blockDim.x;
    float4 z = make_float4(0.f, 0.f, 0.f, 0.f);
    for (int j = i; j < n4; j += stride) out[j] = z;
    if (i < NE) g_counts[i] = 0;
}

__global__ void route_kernel(const void* __restrict__ idx_raw, const float* __restrict__ probs) {
    __shared__ int cnt[NE], base[NE], s_is64;
    const int tid = threadIdx.x;
    const int t = blockIdx.x * 256 + tid;
    if (tid < NE) cnt[tid] = 0;
    if (tid == 0) {
        const int* iw = (const int*)idx_raw;
        int is64 = 1;
        for (int i = 1; i < 64; i += 2)
            if (iw[i] != 0) { is64 = 0; break; }
        s_is64 = is64;
    }
    __syncthreads();

    int e0, e1;
    if (s_is64) {
        const long long* p = (const long long*)idx_raw;
        e0 = (int)p[2*t]; e1 = (int)p[2*t+1];
    } else {
        const int* p = (const int*)idx_raw;
        e0 = p[2*t]; e1 = p[2*t+1];
    }
    float p0 = probs[2*t], p1 = probs[2*t+1];
    if (e0 == e1) p0 += p1;
    int pos0 = atomicAdd(&cnt[e0], 1);
    int pos1 = (e1 != e0) ? atomicAdd(&cnt[e1], 1) : -1;
    __syncthreads();

    if (tid < NE) base[tid] = atomicAdd(&g_counts[tid], cnt[tid]);
    __syncthreads();

    int i0 = e0 * T_TOK + base[e0] + pos0;
    g_tok[i0] = t; g_gate[i0] = p0;
    if (pos1 >= 0) {
        int i1 = e1 * T_TOK + base[e1] + pos1;
        g_tok[i1] = t; g_gate[i1] = p1;
    }
}

__global__ void convert_all_kernel(const float* __restrict__ x,
                                   const float* __restrict__ w1,
                                   const float* __restrict__ w2) {
    const int N4X = (T_TOK * DIM) / 4;
    const int N4W = (NE * FF * DIM) / 4;
    const int total = N4X + 2 * N4W;
    int i = blockIdx.x * blockDim.x + threadIdx.x;
    int stride = gridDim.x * blockDim.x;
    for (int j = i; j < total; j += stride) {
        float4 v; __half2* d;
        if (j < N4X) {
            v = reinterpret_cast<const float4*>(x)[j];
            d = reinterpret_cast<__half2*>(g_xh) + 2 * (size_t)j;
        } else if (j < N4X + N4W) {
            int k = j - N4X;
            v = reinterpret_cast<const float4*>(w1)[k];
            d = reinterpret_cast<__half2*>(g_w1h) + 2 * (size_t)k;
        } else {
            int k = j - N4X - N4W;
            v = reinterpret_cast<const float4*>(w2)[k];
            d = reinterpret_cast<__half2*>(g_w2h) + 2 * (size_t)k;
        }
        d[0] = __floats2half2_rn(v.x, v.y);
        d[1] = __floats2half2_rn(v.z, v.w);
    }
}

// ================== GEMM compute chunk: tile 64x128, warp tile 32x32 ==================
__device__ __forceinline__ void compute_chunk(const __half* As, const __half* Bs,
                                              int wm, int wn, int g, int t4,
                                              float acc[2][4][4]) {
    #pragma unroll
    for (int kk = 0; kk < 2; kk++) {
        const int kb = kk * 16 + t4 * 2;
        uint32_t a[2][4];
        #pragma unroll
        for (int mtl = 0; mtl < 2; mtl++) {
            const int r0 = wm + mtl * 16 + g;
            const __half* p0 = &As[r0 * 40 + kb];
            const __half* p1 = &As[(r0 + 8) * 40 + kb];
            a[mtl][0] = *(const uint32_t*)p0;
            a[mtl][1] = *(const uint32_t*)p1;
            a[mtl][2] = *(const uint32_t*)(p0 + 8);
            a[mtl][3] = *(const uint32_t*)(p1 + 8);
        }
        #pragma unroll
        for (int nt = 0; nt < 4; nt++) {
            const int n = wn + nt * 8 + g;
            const __half* pb = &Bs[n * 40 + kb];
            uint32_t b0 = *(const uint32_t*)pb;
            uint32_t b1 = *(const uint32_t*)(pb + 8);
            mma16816(acc[0][nt], a[0], b0, b1);
            mma16816(acc[1][nt], a[1], b0, b1);
        }
    }
}

// ---------------- GEMM1: H = silu(X_gather @ W1[e]^T), fp16 out ----------------
// grid: (FF/TN, T/TM, NE), 256 threads, 8 warps as 2(M)x4(N), 3 CTAs/SM
__global__ void __launch_bounds__(256, 3) moe_gemm1() {
    const int e = blockIdx.z;
    const int tid = threadIdx.x;

    __shared__ int s_cnt[NE];
    __shared__ int s_tok[TM];
    if (tid < NE) s_cnt[tid] = g_counts[tid];
    __syncthreads();
    const int count = s_cnt[e];
    int offs = 0;
    #pragma unroll
    for (int i = 0; i < NE; i++) offs += (i < e) ? s_cnt[i] : 0;

    const int m0 = blockIdx.y * TM;
    if (m0 >= count) return;
    const int n0 = blockIdx.x * TN;

    __shared__ __half As[2][TM * 40];
    __shared__ __half Bs[2][TN * 40];

    if (tid < TM) {
        int i = m0 + tid;
        s_tok[tid] = g_tok[e * T_TOK + ((i < count) ? i : (count - 1))];
    }
    __syncthreads();

    const int w = tid >> 5, lane = tid & 31;
    const int wm = (w & 1) * 32, wn = (w >> 1) * 32;
    const int g = lane >> 2, t4 = lane & 3;

    float acc[2][4][4];
    #pragma unroll
    for (int i = 0; i < 2; i++)
        #pragma unroll
        for (int j = 0; j < 4; j++)
            #pragma unroll
            for (int q = 0; q < 4; q++) acc[i][j][q] = 0.f;

    // loaders: A 64x32 (1 cp16/thread), B 128x32 (2 cp16/thread)
    const int arow = tid >> 2, ac = (tid & 3) * 8;
    const int brow = tid >> 1, bc = (tid & 1) * 16;
    const __half* a_g = g_xh  + (size_t)s_tok[arow] * DIM + ac;
    const __half* b_g = g_w1h + ((size_t)e * FF + n0 + brow) * DIM + bc;
    __half* a_s0 = &As[0][arow * 40 + ac];
    __half* b_s0 = &Bs[0][brow * 40 + bc];

    #pragma unroll
    for (int s = 0; s < 1; s++) {
        cp16(a_s0, a_g);
        cp16(b_s0, b_g);
        cp16(b_s0 + 8, b_g + 8);
    }
    CP_COMMIT();

    const int KT = DIM / 32;
    for (int kt = 0; kt < KT; kt++) {
        if (kt + 1 < KT) {
            int s = (kt + 1) & 1, k0 = (kt + 1) * 32;
            cp16(a_s0 + s * (TM * 40), a_g + k0);
            cp16(b_s0 + s * (TN * 40), b_g + k0);
            cp16(b_s0 + s * (TN * 40) + 8, b_g + k0 + 8);
            CP_COMMIT();
            CP_WAIT(1);
        } else {
            CP_WAIT(0);
        }
        __syncthreads();
        const int s = kt & 1;
        compute_chunk(As[s], Bs[s], wm, wn, g, t4, acc);
        __syncthreads();
    }

    const int hbase = offs + m0;
    #pragma unroll
    for (int mtl = 0; mtl < 2; mtl++) {
        int r0 = wm + mtl * 16 + g;
        int r1 = r0 + 8;
        #pragma unroll
        for (int nt = 0; nt < 4; nt++) {
            int col = n0 + wn + nt * 8 + t4 * 2;
            if (m0 + r0 < count) {
                __half2 h = __floats2half2_rn(silu_f(acc[mtl][nt][0]), silu_f(acc[mtl][nt][1]));
                *(__half2*)&g_h[(size_t)(hbase + r0) * FF + col] = h;
            }
            if (m0 + r1 < count) {
                __half2 h = __floats2half2_rn(silu_f(acc[mtl][nt][2]), silu_f(acc[mtl][nt][3]));
                *(__half2*)&g_h[(size_t)(hbase + r1) * FF + col] = h;
            }
        }
    }
}

// ---------------- GEMM2: out[tok] += gate * (H @ W2[e]^T) ----------------
// grid: (DIM/TN, T/TM, NE), 256 threads, 3 CTAs/SM
__global__ void __launch_bounds__(256, 3) moe_gemm2(float* __restrict__ out) {
    const int e = blockIdx.z;
    const int tid = threadIdx.x;

    __shared__ int   s_cnt[NE];
    __shared__ int   s_tok[TM];
    __shared__ float s_gate[TM];
    if (tid < NE) s_cnt[tid] = g_counts[tid];
    __syncthreads();
    const int count = s_cnt[e];
    int offs = 0;
    #pragma unroll
    for (int i = 0; i < NE; i++) offs += (i < e) ? s_cnt[i] : 0;

    const int m0 = blockIdx.y * TM;
    if (m0 >= count) return;
    const int n0 = blockIdx.x * TN;

    __shared__ __half As[2][TM * 40];
    __shared__ __half Bs[2][TN * 40];

    if (tid < TM) {
        int i = m0 + tid;
        int ic = (i < count) ? i : (count - 1);
        s_tok [tid] = g_tok [e * T_TOK + ic];
        s_gate[tid] = g_gate[e * T_TOK + ic];
    }
    __syncthreads();

    const int w = tid >> 5, lane = tid & 31;
    const int wm = (w & 1) * 32, wn = (w >> 1) * 32;
    const int g = lane >> 2, t4 = lane & 3;

    float acc[2][4][4];
    #pragma unroll
    for (int i = 0; i < 2; i++)
        #pragma unroll
        for (int j = 0; j < 4; j++)
            #pragma unroll
            for (int q = 0; q < 4; q++) acc[i][j][q] = 0.f;

    const int arow = tid >> 2, ac = (tid & 3) * 8;
    const int brow = tid >> 1, bc = (tid & 1) * 16;
    const int hrow = offs + ((m0 + arow < count) ? m0 + arow : count - 1);
    const __half* a_g = g_h   + (size_t)hrow * FF + ac;
    const __half* b_g = g_w2h + ((size_t)e * DIM + n0 + brow) * FF + bc;
    __half* a_s0 = &As[0][arow * 40 + ac];
    __half* b_s0 = &Bs[0][brow * 40 + bc];

    cp16(a_s0, a_g);
    cp16(b_s0, b_g);
    cp16(b_s0 + 8, b_g + 8);
    CP_COMMIT();

    const int KT = FF / 32;
    for (int kt = 0; kt < KT; kt++) {
        if (kt + 1 < KT) {
            int s = (kt + 1) & 1, k0 = (kt + 1) * 32;
            cp16(a_s0 + s * (TM * 40), a_g + k0);
            cp16(b_s0 + s * (TN * 40), b_g + k0);
            cp16(b_s0 + s * (TN * 40) + 8, b_g + k0 + 8);
            CP_COMMIT();
            CP_WAIT(1);
        } else {
            CP_WAIT(0);
        }
        __syncthreads();
        const int s = kt & 1;
        compute_chunk(As[s], Bs[s], wm, wn, g, t4, acc);
        __syncthreads();
    }

    #pragma unroll
    for (int mtl = 0; mtl < 2; mtl++) {
        int r0 = wm + mtl * 16 + g;
        int r1 = r0 + 8;
        #pragma unroll
        for (int nt = 0; nt < 4; nt++) {
            int col = n0 + wn + nt * 8 + t4 * 2;
            if (m0 + r0 < count) {
                float gate = s_gate[r0];
                float2 v = make_float2(gate * acc[mtl][nt][0], gate * acc[mtl][nt][1]);
                atomicAdd(reinterpret_cast<float2*>(&out[(size_t)s_tok[r0] * DIM + col]), v);
            }
            if (m0 + r1 < count) {
                float gate = s_gate[r1];
                float2 v = make_float2(gate * acc[mtl][nt][2], gate * acc[mtl][nt][3]);
                atomicAdd(reinterpret_cast<float2*>(&out[(size_t)s_tok[r1] * DIM + col]), v);
            }
        }
    }
}

// ---------------- launcher ----------------
// ncu (-s 5 -c 1) captures overall #6 == our #4 -> moe_gemm1 in the slot:
//   zero+clear(1), route(2), convert_all(3), GEMM1(4)*, GEMM2(5)
extern "C" void kernel_launch(void* const* d_in, const int* in_sizes, int n_in,
                              void* d_out, int out_size) {
    const float* x     = (const float*)d_in[0];
    const float* probs = (const float*)d_in[1];
    const void*  idx   = d_in[2];
    const float* w1    = (const float*)d_in[3];
    const float* w2    = (const float*)d_in[4];
    float* out = (float*)d_out;

    zero_out_kernel<<<8192, 256>>>((float4*)out, out_size / 4);
    route_kernel<<<T_TOK / 256, 256>>>(idx, probs);
    convert_all_kernel<<<8192, 256>>>(x, w1, w2);

    dim3 g1(FF / TN, T_TOK / TM, NE);
    moe_gemm1<<<g1, 256>>>();

    dim3 g2(DIM / TN, T_TOK / TM, NE);
    moe_gemm2<<<g2, 256>>>(out);
}

// round 16
// speedup vs baseline: 1.4126x; 1.4126x over previous
#include <cuda_runtime.h>
#include <cuda_fp16.h>
#include <stdint.h>

#define T_TOK 32768
#define DIM   1024
#define FF    2048
#define NE    8

// ---------------- device scratch ----------------
__device__ int    g_counts[NE];
__device__ int    g_tok [NE * T_TOK];
__device__ float  g_gate[NE * T_TOK];
__device__ __half g_xh [(size_t)T_TOK * DIM];
__device__ __half g_w1h[(size_t)NE * FF * DIM];
__device__ __half g_w2h[(size_t)NE * DIM * FF];
__device__ __half g_h  [(size_t)T_TOK * 2 * FF];

// ---------------- helpers ----------------
__device__ __forceinline__ void cp16(void* smem, const void* gmem) {
    uint32_t s = (uint32_t)__cvta_generic_to_shared(smem);
    asm volatile("cp.async.cg.shared.global [%0], [%1], 16;\n" :: "r"(s), "l"(gmem));
}
#define CP_COMMIT() asm volatile("cp.async.commit_group;\n" ::: "memory")
#define CP_WAIT(n)  asm volatile("cp.async.wait_group %0;\n" :: "n"(n) : "memory")

#define LDSM4(r0, r1, r2, r3, addr) \
    asm volatile("ldmatrix.sync.aligned.m8n8.x4.shared.b16 {%0,%1,%2,%3}, [%4];" \
                 : "=r"(r0), "=r"(r1), "=r"(r2), "=r"(r3) : "r"(addr))

__device__ __forceinline__ void mma16816(float* c, const uint32_t* a, uint32_t b0, uint32_t b1) {
    asm volatile(
        "mma.sync.aligned.m16n8k16.row.col.f32.f16.f16.f32 "
        "{%0,%1,%2,%3}, {%4,%5,%6,%7}, {%8,%9}, {%0,%1,%2,%3};\n"
        : "+f"(c[0]), "+f"(c[1]), "+f"(c[2]), "+f"(c[3])
        : "r"(a[0]), "r"(a[1]), "r"(a[2]), "r"(a[3]), "r"(b0), "r"(b1));
}

__device__ __forceinline__ float silu_f(float v) {
    return v * __frcp_rn(1.0f + __expf(-v));
}

// ---------------- prep kernels ----------------
__global__ void zero_out_kernel(float4* out, int n4) {
    int i = blockIdx.x * blockDim.x + threadIdx.x;
    int stride = gridDim.x * blockDim.x;
    float4 z = make_float4(0.f, 0.f, 0.f, 0.f);
    for (int j = i; j < n4; j += stride) out[j] = z;
    if (i < NE) g_counts[i] = 0;
}

__global__ void route_kernel(const void* __restrict__ idx_raw, const float* __restrict__ probs) {
    __shared__ int cnt[NE], base[NE], s_is64;
    const int tid = threadIdx.x;
    const int t = blockIdx.x * 256 + tid;
    if (tid < NE) cnt[tid] = 0;
    if (tid == 0) {
        const int* iw = (const int*)idx_raw;
        int is64 = 1;
        for (int i = 1; i < 64; i += 2)
            if (iw[i] != 0) { is64 = 0; break; }
        s_is64 = is64;
    }
    __syncthreads();

    int e0, e1;
    if (s_is64) {
        const long long* p = (const long long*)idx_raw;
        e0 = (int)p[2*t]; e1 = (int)p[2*t+1];
    } else {
        const int* p = (const int*)idx_raw;
        e0 = p[2*t]; e1 = p[2*t+1];
    }
    float p0 = probs[2*t], p1 = probs[2*t+1];
    if (e0 == e1) p0 += p1;
    int pos0 = atomicAdd(&cnt[e0], 1);
    int pos1 = (e1 != e0) ? atomicAdd(&cnt[e1], 1) : -1;
    __syncthreads();

    if (tid < NE) base[tid] = atomicAdd(&g_counts[tid], cnt[tid]);
    __syncthreads();

    int i0 = e0 * T_TOK + base[e0] + pos0;
    g_tok[i0] = t; g_gate[i0] = p0;
    if (pos1 >= 0) {
        int i1 = e1 * T_TOK + base[e1] + pos1;
        g_tok[i1] = t; g_gate[i1] = p1;
    }
}

__global__ void convert_all_kernel(const float* __restrict__ x,
                                   const float* __restrict__ w1,
                                   const float* __restrict__ w2) {
    const int N4X = (T_TOK * DIM) / 4;
    const int N4W = (NE * FF * DIM) / 4;
    const int total = N4X + 2 * N4W;
    int i = blockIdx.x * blockDim.x + threadIdx.x;
    int stride = gridDim.x * blockDim.x;
    for (int j = i; j < total; j += stride) {
        float4 v; __half2* d;
        if (j < N4X) {
            v = reinterpret_cast<const float4*>(x)[j];
            d = reinterpret_cast<__half2*>(g_xh) + 2 * (size_t)j;
        } else if (j < N4X + N4W) {
            int k = j - N4X;
            v = reinterpret_cast<const float4*>(w1)[k];
            d = reinterpret_cast<__half2*>(g_w1h) + 2 * (size_t)k;
        } else {
            int k = j - N4X - N4W;
            v = reinterpret_cast<const float4*>(w2)[k];
            d = reinterpret_cast<__half2*>(g_w2h) + 2 * (size_t)k;
        }
        d[0] = __floats2half2_rn(v.x, v.y);
        d[1] = __floats2half2_rn(v.z, v.w);
    }
}

// ================== GEMM compute chunk — ldmatrix fragment loads ==================
// Identical math/order to the R9 scalar core; only the fragment loads change:
// 12x ldmatrix.x4 per warp-chunk instead of 48x LDS.32.
// 40-half (80B) row stride => 8 consecutive rows hit distinct 16B banks.
__device__ __forceinline__ void compute_chunk(uint32_t sA, uint32_t sB,
                                              int wm, int wn, int lane,
                                              float acc[2][8][4]) {
    const int la  = lane & 15;            // A: row within 16-row block
    const int lh  = (lane >> 4) * 8;      // A: k-col half (0/8)
    const int lb8 = lane & 7;             // B: row within 8-row block
    const int lbr = ((lane >> 4) & 1) * 8;// B: n-block select (0/8)
    const int lbc = ((lane >> 3) & 1) * 8;// B: k-col half (0/8)
    #pragma unroll
    for (int kk = 0; kk < 2; kk++) {
        const int kb = kk * 16;
        uint32_t a[2][4];
        #pragma unroll
        for (int mtl = 0; mtl < 2; mtl++) {
            uint32_t addr = sA + (uint32_t)(((wm + mtl * 16 + la) * 40 + kb + lh) * 2);
            LDSM4(a[mtl][0], a[mtl][1], a[mtl][2], a[mtl][3], addr);
        }
        #pragma unroll
        for (int p = 0; p < 4; p++) {
            uint32_t b0, b1, b2, b3;
            uint32_t addr = sB + (uint32_t)(((wn + p * 16 + lb8 + lbr) * 40 + kb + lbc) * 2);
            LDSM4(b0, b1, b2, b3, addr);
            mma16816(acc[0][2 * p],     a[0], b0, b1);
            mma16816(acc[0][2 * p + 1], a[0], b2, b3);
            mma16816(acc[1][2 * p],     a[1], b0, b1);
            mma16816(acc[1][2 * p + 1], a[1], b2, b3);
        }
    }
}

// ---------------- GEMM1: H = silu(X_gather @ W1[e]^T), fp16 out ----------------
// grid: (FF/128, T/128, NE), 256 threads  [R12 skeleton, ldmatrix frags]
__global__ void __launch_bounds__(256, 2) moe_gemm1() {
    const int e = blockIdx.z;
    const int tid = threadIdx.x;

    __shared__ int s_cnt[NE];
    if (tid < NE) s_cnt[tid] = g_counts[tid];
    __syncthreads();
    const int count = s_cnt[e];
    int offs = 0;
    #pragma unroll
    for (int i = 0; i < NE; i++) offs += (i < e) ? s_cnt[i] : 0;

    const int m0 = blockIdx.y * 128;
    if (m0 >= count) return;
    const int n0 = blockIdx.x * 128;

    __shared__ __half As[2][128 * 40];
    __shared__ __half Bs[2][128 * 40];
    __shared__ int s_tok[128];

    if (tid < 128) {
        int i = m0 + tid;
        s_tok[tid] = g_tok[e * T_TOK + ((i < count) ? i : (count - 1))];
    }
    __syncthreads();

    const int w = tid >> 5, lane = tid & 31;
    const int wm = (w & 3) * 32, wn = (w >> 2) * 64;
    const int g = lane >> 2, t4 = lane & 3;

    const uint32_t sA[2] = { (uint32_t)__cvta_generic_to_shared(&As[0][0]),
                             (uint32_t)__cvta_generic_to_shared(&As[1][0]) };
    const uint32_t sB[2] = { (uint32_t)__cvta_generic_to_shared(&Bs[0][0]),
                             (uint32_t)__cvta_generic_to_shared(&Bs[1][0]) };

    float acc[2][8][4];
    #pragma unroll
    for (int i = 0; i < 2; i++)
        #pragma unroll
        for (int j = 0; j < 8; j++)
            #pragma unroll
            for (int q = 0; q < 4; q++) acc[i][j][q] = 0.f;

    const int row_l = tid >> 2;
    const int colh  = (tid & 3) * 8;

    #pragma unroll
    for (int u = 0; u < 2; u++) {
        int row = row_l + u * 64;
        cp16(&As[0][row * 40 + colh], g_xh  + (size_t)s_tok[row] * DIM + colh);
        cp16(&Bs[0][row * 40 + colh], g_w1h + ((size_t)e * FF + n0 + row) * DIM + colh);
    }
    CP_COMMIT();

    const int KT = DIM / 32;
    for (int kt = 0; kt < KT; kt++) {
        if (kt + 1 < KT) {
            int s = (kt + 1) & 1, k0 = (kt + 1) * 32;
            #pragma unroll
            for (int u = 0; u < 2; u++) {
                int row = row_l + u * 64;
                cp16(&As[s][row * 40 + colh], g_xh  + (size_t)s_tok[row] * DIM + k0 + colh);
                cp16(&Bs[s][row * 40 + colh], g_w1h + ((size_t)e * FF + n0 + row) * DIM + k0 + colh);
            }
            CP_COMMIT();
            CP_WAIT(1);
        } else {
            CP_WAIT(0);
        }
        __syncthreads();
        const int s = kt & 1;
        compute_chunk(sA[s], sB[s], wm, wn, lane, acc);
        __syncthreads();
    }

    const int hbase = offs + m0;
    #pragma unroll
    for (int mtl = 0; mtl < 2; mtl++) {
        int r0 = wm + mtl * 16 + g;
        int r1 = r0 + 8;
        #pragma unroll
        for (int nt = 0; nt < 8; nt++) {
            int col = n0 + wn + nt * 8 + t4 * 2;
            if (m0 + r0 < count) {
                __half2 h = __floats2half2_rn(silu_f(acc[mtl][nt][0]), silu_f(acc[mtl][nt][1]));
                *(__half2*)&g_h[(size_t)(hbase + r0) * FF + col] = h;
            }
            if (m0 + r1 < count) {
                __half2 h = __floats2half2_rn(silu_f(acc[mtl][nt][2]), silu_f(acc[mtl][nt][3]));
                *(__half2*)&g_h[(size_t)(hbase + r1) * FF + col] = h;
            }
        }
    }
}

// ---------------- GEMM2: out[tok] += gate * (H @ W2[e]^T) ----------------
// grid: (DIM/128, T/128, NE), 256 threads  [R12 skeleton, ldmatrix frags]
__global__ void __launch_bounds__(256, 2) moe_gemm2(float* __restrict__ out) {
    const int e = blockIdx.z;
    const int tid = threadIdx.x;

    __shared__ int s_cnt[NE];
    if (tid < NE) s_cnt[tid] = g_counts[tid];
    __syncthreads();
    const int count = s_cnt[e];
    int offs = 0;
    #pragma unroll
    for (int i = 0; i < NE; i++) offs += (i < e) ? s_cnt[i] : 0;

    const int m0 = blockIdx.y * 128;
    if (m0 >= count) return;
    const int n0 = blockIdx.x * 128;

    __shared__ __half As[2][128 * 40];
    __shared__ __half Bs[2][128 * 40];
    __shared__ int   s_tok[128];
    __shared__ float s_gate[128];

    if (tid < 128) {
        int i = m0 + tid;
        int ic = (i < count) ? i : (count - 1);
        s_tok [tid] = g_tok [e * T_TOK + ic];
        s_gate[tid] = g_gate[e * T_TOK + ic];
    }
    __syncthreads();

    const int w = tid >> 5, lane = tid & 31;
    const int wm = (w & 3) * 32, wn = (w >> 2) * 64;
    const int g = lane >> 2, t4 = lane & 3;

    const uint32_t sA[2] = { (uint32_t)__cvta_generic_to_shared(&As[0][0]),
                             (uint32_t)__cvta_generic_to_shared(&As[1][0]) };
    const uint32_t sB[2] = { (uint32_t)__cvta_generic_to_shared(&Bs[0][0]),
                             (uint32_t)__cvta_generic_to_shared(&Bs[1][0]) };

    float acc[2][8][4];
    #pragma unroll
    for (int i = 0; i < 2; i++)
        #pragma unroll
        for (int j = 0; j < 8; j++)
            #pragma unroll
            for (int q = 0; q < 4; q++) acc[i][j][q] = 0.f;

    const int row_l = tid >> 2;
    const int colh  = (tid & 3) * 8;
    int hrow[2];
    #pragma unroll
    for (int u = 0; u < 2; u++) {
        int i = m0 + row_l + u * 64;
        hrow[u] = offs + ((i < count) ? i : (count - 1));
    }

    #pragma unroll
    for (int u = 0; u < 2; u++) {
        int row = row_l + u * 64;
        cp16(&As[0][row * 40 + colh], g_h   + (size_t)hrow[u] * FF + colh);
        cp16(&Bs[0][row * 40 + colh], g_w2h + ((size_t)e * DIM + n0 + row) * FF + colh);
    }
    CP_COMMIT();

    const int KT = FF / 32;
    for (int kt = 0; kt < KT; kt++) {
        if (kt + 1 < KT) {
            int s = (kt + 1) & 1, k0 = (kt + 1) * 32;
            #pragma unroll
            for (int u = 0; u < 2; u++) {
                int row = row_l + u * 64;
                cp16(&As[s][row * 40 + colh], g_h   + (size_t)hrow[u] * FF + k0 + colh);
                cp16(&Bs[s][row * 40 + colh], g_w2h + ((size_t)e * DIM + n0 + row) * FF + k0 + colh);
            }
            CP_COMMIT();
            CP_WAIT(1);
        } else {
            CP_WAIT(0);
        }
        __syncthreads();
        const int s = kt & 1;
        compute_chunk(sA[s], sB[s], wm, wn, lane, acc);
        __syncthreads();
    }

    #pragma unroll
    for (int mtl = 0; mtl < 2; mtl++) {
        int r0 = wm + mtl * 16 + g;
        int r1 = r0 + 8;
        #pragma unroll
        for (int nt = 0; nt < 8; nt++) {
            int col = n0 + wn + nt * 8 + t4 * 2;
            if (m0 + r0 < count) {
                float gate = s_gate[r0];
                float2 v = make_float2(gate * acc[mtl][nt][0], gate * acc[mtl][nt][1]);
                atomicAdd(reinterpret_cast<float2*>(&out[(size_t)s_tok[r0] * DIM + col]), v);
            }
            if (m0 + r1 < count) {
                float gate = s_gate[r1];
                float2 v = make_float2(gate * acc[mtl][nt][2], gate * acc[mtl][nt][3]);
                atomicAdd(reinterpret_cast<float2*>(&out[(size_t)s_tok[r1] * DIM + col]), v);
            }
        }
    }
}

// ---------------- launcher ----------------
// ncu (-s 5 -c 1) captures overall #6 == our #4 -> moe_gemm1 in the slot:
//   zero+clear(1), route(2), convert_all(3), GEMM1(4)*, GEMM2(5)
extern "C" void kernel_launch(void* const* d_in, const int* in_sizes, int n_in,
                              void* d_out, int out_size) {
    const float* x     = (const float*)d_in[0];
    const float* probs = (const float*)d_in[1];
    const void*  idx   = d_in[2];
    const float* w1    = (const float*)d_in[3];
    const float* w2    = (const float*)d_in[4];
    float* out = (float*)d_out;

    zero_out_kernel<<<8192, 256>>>((float4*)out, out_size / 4);
    route_kernel<<<T_TOK / 256, 256>>>(idx, probs);
    convert_all_kernel<<<8192, 256>>>(x, w1, w2);

    dim3 g1(FF / 128, T_TOK / 128, NE);
    moe_gemm1<<<g1, 256>>>();

    dim3 g2(DIM / 128, T_TOK / 128, NE);
    moe_gemm2<<<g2, 256>>>(out);
}

// round 17
// speedup vs baseline: 1.4412x; 1.0203x over previous
#include <cuda_runtime.h>
#include <cuda_fp16.h>
#include <stdint.h>

#define T_TOK 32768
#define DIM   1024
#define FF    2048
#define NE    8

// ---------------- device scratch ----------------
__device__ int    g_counts[NE];
__device__ int    g_tok [NE * T_TOK];
__device__ float  g_gate[NE * T_TOK];
__device__ __half g_xh [(size_t)T_TOK * DIM];
__device__ __half g_w1h[(size_t)NE * FF * DIM];
__device__ __half g_w2h[(size_t)NE * DIM * FF];
__device__ __half g_h  [(size_t)T_TOK * 2 * FF];

// ---------------- helpers ----------------
__device__ __forceinline__ void cp16(void* smem, const void* gmem) {
    uint32_t s = (uint32_t)__cvta_generic_to_shared(smem);
    asm volatile("cp.async.cg.shared.global [%0], [%1], 16;\n" :: "r"(s), "l"(gmem));
}
#define CP_COMMIT() asm volatile("cp.async.commit_group;\n" ::: "memory")
#define CP_WAIT(n)  asm volatile("cp.async.wait_group %0;\n" :: "n"(n) : "memory")

#define LDSM4(r0, r1, r2, r3, addr) \
    asm volatile("ldmatrix.sync.aligned.m8n8.x4.shared.b16 {%0,%1,%2,%3}, [%4];" \
                 : "=r"(r0), "=r"(r1), "=r"(r2), "=r"(r3) : "r"(addr))

__device__ __forceinline__ void mma16816(float* c, const uint32_t* a, uint32_t b0, uint32_t b1) {
    asm volatile(
        "mma.sync.aligned.m16n8k16.row.col.f32.f16.f16.f32 "
        "{%0,%1,%2,%3}, {%4,%5,%6,%7}, {%8,%9}, {%0,%1,%2,%3};\n"
        : "+f"(c[0]), "+f"(c[1]), "+f"(c[2]), "+f"(c[3])
        : "r"(a[0]), "r"(a[1]), "r"(a[2]), "r"(a[3]), "r"(b0), "r"(b1));
}

__device__ __forceinline__ float silu_f(float v) {
    return v * __frcp_rn(1.0f + __expf(-v));
}

// ---------------- prep kernels ----------------
__global__ void zero_out_kernel(float4* out, int n4) {
    int i = blockIdx.x * blockDim.x + threadIdx.x;
    int stride = gridDim.x * blockDim.x;
    float4 z = make_float4(0.f, 0.f, 0.f, 0.f);
    for (int j = i; j < n4; j += stride) out[j] = z;
    if (i < NE) g_counts[i] = 0;
}

__global__ void route_kernel(const void* __restrict__ idx_raw, const float* __restrict__ probs) {
    __shared__ int cnt[NE], base[NE], s_is64;
    const int tid = threadIdx.x;
    const int t = blockIdx.x * 256 + tid;
    if (tid < NE) cnt[tid] = 0;
    if (tid == 0) {
        const int* iw = (const int*)idx_raw;
        int is64 = 1;
        for (int i = 1; i < 64; i += 2)
            if (iw[i] != 0) { is64 = 0; break; }
        s_is64 = is64;
    }
    __syncthreads();

    int e0, e1;
    if (s_is64) {
        const long long* p = (const long long*)idx_raw;
        e0 = (int)p[2*t]; e1 = (int)p[2*t+1];
    } else {
        const int* p = (const int*)idx_raw;
        e0 = p[2*t]; e1 = p[2*t+1];
    }
    float p0 = probs[2*t], p1 = probs[2*t+1];
    if (e0 == e1) p0 += p1;
    int pos0 = atomicAdd(&cnt[e0], 1);
    int pos1 = (e1 != e0) ? atomicAdd(&cnt[e1], 1) : -1;
    __syncthreads();

    if (tid < NE) base[tid] = atomicAdd(&g_counts[tid], cnt[tid]);
    __syncthreads();

    int i0 = e0 * T_TOK + base[e0] + pos0;
    g_tok[i0] = t; g_gate[i0] = p0;
    if (pos1 >= 0) {
        int i1 = e1 * T_TOK + base[e1] + pos1;
        g_tok[i1] = t; g_gate[i1] = p1;
    }
}

__global__ void convert_all_kernel(const float* __restrict__ x,
                                   const float* __restrict__ w1,
                                   const float* __restrict__ w2) {
    const int N4X = (T_TOK * DIM) / 4;
    const int N4W = (NE * FF * DIM) / 4;
    const int total = N4X + 2 * N4W;
    int i = blockIdx.x * blockDim.x + threadIdx.x;
    int stride = gridDim.x * blockDim.x;
    for (int j = i; j < total; j += stride) {
        float4 v; __half2* d;
        if (j < N4X) {
            v = reinterpret_cast<const float4*>(x)[j];
            d = reinterpret_cast<__half2*>(g_xh) + 2 * (size_t)j;
        } else if (j < N4X + N4W) {
            int k = j - N4X;
            v = reinterpret_cast<const float4*>(w1)[k];
            d = reinterpret_cast<__half2*>(g_w1h) + 2 * (size_t)k;
        } else {
            int k = j - N4X - N4W;
            v = reinterpret_cast<const float4*>(w2)[k];
            d = reinterpret_cast<__half2*>(g_w2h) + 2 * (size_t)k;
        }
        d[0] = __floats2half2_rn(v.x, v.y);
        d[1] = __floats2half2_rn(v.z, v.w);
    }
}

// ================== GEMM compute chunk — ldmatrix frags + embedded fill ==================
// Same math/order as the R16 winner; `fill` (next chunk's cp.async + commit) is
// issued between the kk=0 and kk=1 halves so LSU/L2 work hides under MMAs.
template <typename F>
__device__ __forceinline__ void compute_chunk(uint32_t sA, uint32_t sB,
                                              int wm, int wn, int lane,
                                              float acc[2][8][4], F&& fill) {
    const int la  = lane & 15;
    const int lh  = (lane >> 4) * 8;
    const int lb8 = lane & 7;
    const int lbr = ((lane >> 4) & 1) * 8;
    const int lbc = ((lane >> 3) & 1) * 8;
    #pragma unroll
    for (int kk = 0; kk < 2; kk++) {
        const int kb = kk * 16;
        uint32_t a[2][4];
        #pragma unroll
        for (int mtl = 0; mtl < 2; mtl++) {
            uint32_t addr = sA + (uint32_t)(((wm + mtl * 16 + la) * 40 + kb + lh) * 2);
            LDSM4(a[mtl][0], a[mtl][1], a[mtl][2], a[mtl][3], addr);
        }
        #pragma unroll
        for (int p = 0; p < 4; p++) {
            uint32_t b0, b1, b2, b3;
            uint32_t addr = sB + (uint32_t)(((wn + p * 16 + lb8 + lbr) * 40 + kb + lbc) * 2);
            LDSM4(b0, b1, b2, b3, addr);
            mma16816(acc[0][2 * p],     a[0], b0, b1);
            mma16816(acc[0][2 * p + 1], a[0], b2, b3);
            mma16816(acc[1][2 * p],     a[1], b0, b1);
            mma16816(acc[1][2 * p + 1], a[1], b2, b3);
        }
        if (kk == 0) fill();
    }
}

// ---------------- GEMM1: H = silu(X_gather @ W1[e]^T), fp16 out ----------------
// grid: (FF/128, T/128, NE), 256 threads — single barrier/chunk, fill-in-compute
__global__ void __launch_bounds__(256, 2) moe_gemm1() {
    const int e = blockIdx.z;
    const int tid = threadIdx.x;

    __shared__ int s_cnt[NE];
    if (tid < NE) s_cnt[tid] = g_counts[tid];
    __syncthreads();
    const int count = s_cnt[e];
    int offs = 0;
    #pragma unroll
    for (int i = 0; i < NE; i++) offs += (i < e) ? s_cnt[i] : 0;

    const int m0 = blockIdx.y * 128;
    if (m0 >= count) return;
    const int n0 = blockIdx.x * 128;

    __shared__ __half As[2][128 * 40];
    __shared__ __half Bs[2][128 * 40];
    __shared__ int s_tok[128];

    if (tid < 128) {
        int i = m0 + tid;
        s_tok[tid] = g_tok[e * T_TOK + ((i < count) ? i : (count - 1))];
    }
    __syncthreads();

    const int w = tid >> 5, lane = tid & 31;
    const int wm = (w & 3) * 32, wn = (w >> 2) * 64;
    const int g = lane >> 2, t4 = lane & 3;

    const uint32_t sA[2] = { (uint32_t)__cvta_generic_to_shared(&As[0][0]),
                             (uint32_t)__cvta_generic_to_shared(&As[1][0]) };
    const uint32_t sB[2] = { (uint32_t)__cvta_generic_to_shared(&Bs[0][0]),
                             (uint32_t)__cvta_generic_to_shared(&Bs[1][0]) };

    float acc[2][8][4];
    #pragma unroll
    for (int i = 0; i < 2; i++)
        #pragma unroll
        for (int j = 0; j < 8; j++)
            #pragma unroll
            for (int q = 0; q < 4; q++) acc[i][j][q] = 0.f;

    const int row_l = tid >> 2;
    const int colh  = (tid & 3) * 8;
    const __half* a_g0 = g_xh  + (size_t)s_tok[row_l] * DIM + colh;
    const __half* a_g1 = g_xh  + (size_t)s_tok[row_l + 64] * DIM + colh;
    const __half* b_g0 = g_w1h + ((size_t)e * FF + n0 + row_l) * DIM + colh;
    const __half* b_g1 = g_w1h + ((size_t)e * FF + n0 + row_l + 64) * DIM + colh;

    auto fill_st = [&](int s, int kt) {
        int k0 = kt * 32;
        cp16(&As[s][row_l * 40 + colh],        a_g0 + k0);
        cp16(&As[s][(row_l + 64) * 40 + colh], a_g1 + k0);
        cp16(&Bs[s][row_l * 40 + colh],        b_g0 + k0);
        cp16(&Bs[s][(row_l + 64) * 40 + colh], b_g1 + k0);
    };

    const int KT = DIM / 32;
    fill_st(0, 0); CP_COMMIT();

    for (int kt = 0; kt < KT; kt++) {
        CP_WAIT(0);
        __syncthreads();
        const int s = kt & 1;
        compute_chunk(sA[s], sB[s], wm, wn, lane, acc,
                      [&] { if (kt + 1 < KT) { fill_st(s ^ 1, kt + 1); CP_COMMIT(); } });
    }

    const int hbase = offs + m0;
    #pragma unroll
    for (int mtl = 0; mtl < 2; mtl++) {
        int r0 = wm + mtl * 16 + g;
        int r1 = r0 + 8;
        #pragma unroll
        for (int nt = 0; nt < 8; nt++) {
            int col = n0 + wn + nt * 8 + t4 * 2;
            if (m0 + r0 < count) {
                __half2 h = __floats2half2_rn(silu_f(acc[mtl][nt][0]), silu_f(acc[mtl][nt][1]));
                *(__half2*)&g_h[(size_t)(hbase + r0) * FF + col] = h;
            }
            if (m0 + r1 < count) {
                __half2 h = __floats2half2_rn(silu_f(acc[mtl][nt][2]), silu_f(acc[mtl][nt][3]));
                *(__half2*)&g_h[(size_t)(hbase + r1) * FF + col] = h;
            }
        }
    }
}

// ---------------- GEMM2: out[tok] += gate * (H @ W2[e]^T) ----------------
// grid: (DIM/128, T/128, NE), 256 threads — single barrier/chunk, fill-in-compute
__global__ void __launch_bounds__(256, 2) moe_gemm2(float* __restrict__ out) {
    const int e = blockIdx.z;
    const int tid = threadIdx.x;

    __shared__ int s_cnt[NE];
    if (tid < NE) s_cnt[tid] = g_counts[tid];
    __syncthreads();
    const int count = s_cnt[e];
    int offs = 0;
    #pragma unroll
    for (int i = 0; i < NE; i++) offs += (i < e) ? s_cnt[i] : 0;

    const int m0 = blockIdx.y * 128;
    if (m0 >= count) return;
    const int n0 = blockIdx.x * 128;

    __shared__ __half As[2][128 * 40];
    __shared__ __half Bs[2][128 * 40];
    __shared__ int   s_tok[128];
    __shared__ float s_gate[128];

    if (tid < 128) {
        int i = m0 + tid;
        int ic = (i < count) ? i : (count - 1);
        s_tok [tid] = g_tok [e * T_TOK + ic];
        s_gate[tid] = g_gate[e * T_TOK + ic];
    }
    __syncthreads();

    const int w = tid >> 5, lane = tid & 31;
    const int wm = (w & 3) * 32, wn = (w >> 2) * 64;
    const int g = lane >> 2, t4 = lane & 3;

    const uint32_t sA[2] = { (uint32_t)__cvta_generic_to_shared(&As[0][0]),
                             (uint32_t)__cvta_generic_to_shared(&As[1][0]) };
    const uint32_t sB[2] = { (uint32_t)__cvta_generic_to_shared(&Bs[0][0]),
                             (uint32_t)__cvta_generic_to_shared(&Bs[1][0]) };

    float acc[2][8][4];
    #pragma unroll
    for (int i = 0; i < 2; i++)
        #pragma unroll
        for (int j = 0; j < 8; j++)
            #pragma unroll
            for (int q = 0; q < 4; q++) acc[i][j][q] = 0.f;

    const int row_l = tid >> 2;
    const int colh  = (tid & 3) * 8;
    int hrow[2];
    #pragma unroll
    for (int u = 0; u < 2; u++) {
        int i = m0 + row_l + u * 64;
        hrow[u] = offs + ((i < count) ? i : (count - 1));
    }
    const __half* a_g0 = g_h   + (size_t)hrow[0] * FF + colh;
    const __half* a_g1 = g_h   + (size_t)hrow[1] * FF + colh;
    const __half* b_g0 = g_w2h + ((size_t)e * DIM + n0 + row_l) * FF + colh;
    const __half* b_g1 = g_w2h + ((size_t)e * DIM + n0 + row_l + 64) * FF + colh;

    auto fill_st = [&](int s, int kt) {
        int k0 = kt * 32;
        cp16(&As[s][row_l * 40 + colh],        a_g0 + k0);
        cp16(&As[s][(row_l + 64) * 40 + colh], a_g1 + k0);
        cp16(&Bs[s][row_l * 40 + colh],        b_g0 + k0);
        cp16(&Bs[s][(row_l + 64) * 40 + colh], b_g1 + k0);
    };

    const int KT = FF / 32;
    fill_st(0, 0); CP_COMMIT();

    for (int kt = 0; kt < KT; kt++) {
        CP_WAIT(0);
        __syncthreads();
        const int s = kt & 1;
        compute_chunk(sA[s], sB[s], wm, wn, lane, acc,
                      [&] { if (kt + 1 < KT) { fill_st(s ^ 1, kt + 1); CP_COMMIT(); } });
    }

    #pragma unroll
    for (int mtl = 0; mtl < 2; mtl++) {
        int r0 = wm + mtl * 16 + g;
        int r1 = r0 + 8;
        #pragma unroll
        for (int nt = 0; nt < 8; nt++) {
            int col = n0 + wn + nt * 8 + t4 * 2;
            if (m0 + r0 < count) {
                float gate = s_gate[r0];
                float2 v = make_float2(gate * acc[mtl][nt][0], gate * acc[mtl][nt][1]);
                atomicAdd(reinterpret_cast<float2*>(&out[(size_t)s_tok[r0] * DIM + col]), v);
            }
            if (m0 + r1 < count) {
                float gate = s_gate[r1];
                float2 v = make_float2(gate * acc[mtl][nt][2], gate * acc[mtl][nt][3]);
                atomicAdd(reinterpret_cast<float2*>(&out[(size_t)s_tok[r1] * DIM + col]), v);
            }
        }
    }
}

// ---------------- launcher ----------------
// ncu (-s 5 -c 1) captures overall #6 == our #4 -> moe_gemm1 in the slot:
//   zero+clear(1), route(2), convert_all(3), GEMM1(4)*, GEMM2(5)
extern "C" void kernel_launch(void* const* d_in, const int* in_sizes, int n_in,
                              void* d_out, int out_size) {
    const float* x     = (const float*)d_in[0];
    const float* probs = (const float*)d_in[1];
    const void*  idx   = d_in[2];
    const float* w1    = (const float*)d_in[3];
    const float* w2    = (const float*)d_in[4];
    float* out = (float*)d_out;

    zero_out_kernel<<<8192, 256>>>((float4*)out, out_size / 4);
    route_kernel<<<T_TOK / 256, 256>>>(idx, probs);
    convert_all_kernel<<<8192, 256>>>(x, w1, w2);

    dim3 g1(FF / 128, T_TOK / 128, NE);
    moe_gemm1<<<g1, 256>>>();

    dim3 g2(DIM / 128, T_TOK / 128, NE);
    moe_gemm2<<<g2, 256>>>(out);
}